// round 3
// baseline (speedup 1.0000x reference)
#include <cuda_runtime.h>
#include <cstdint>

#define HID   16
#define BATCH 2048
#define SEQT  2048
#define FUT   32
#define NOUT  (FUT + 1)

typedef unsigned long long ull;

// ---------- packed f32x2 helpers (sm_103a) ----------
__device__ __forceinline__ ull pack2(float lo, float hi) {
    ull r;
    asm("mov.b64 %0, {%1, %2};" : "=l"(r) : "f"(lo), "f"(hi));
    return r;
}
__device__ __forceinline__ void unpack2(ull v, float& lo, float& hi) {
    asm("mov.b64 {%0, %1}, %2;" : "=f"(lo), "=f"(hi) : "l"(v));
}
__device__ __forceinline__ ull fma2(ull a, ull b, ull c) {
    ull d;
    asm("fma.rn.f32x2 %0, %1, %2, %3;" : "=l"(d) : "l"(a), "l"(b), "l"(c));
    return d;
}
__device__ __forceinline__ ull add2(ull a, ull b) {
    ull d;
    asm("add.rn.f32x2 %0, %1, %2;" : "=l"(d) : "l"(a), "l"(b));
    return d;
}

// ---------- fast activations ----------
__device__ __forceinline__ float tanh_ap(float x) {
    float y;
    asm("tanh.approx.f32 %0, %1;" : "=f"(y) : "f"(x));
    return y;
}
__device__ __forceinline__ float sigm(float x) {
    return fmaf(0.5f, tanh_ap(0.5f * x), 0.5f);
}

// One warp = one batch element.
// lane = g*16 + j : g selects gate pair {0:(i,f), 1:(g,o)}, j = hidden unit.
__global__ void __launch_bounds__(64, 7)
lstm_net_kernel(const float* __restrict__ x,
                const float* __restrict__ Wih1, const float* __restrict__ Whh1,
                const float* __restrict__ bih1, const float* __restrict__ bhh1,
                const float* __restrict__ Wih2, const float* __restrict__ Whh2,
                const float* __restrict__ bih2, const float* __restrict__ bhh2,
                const float* __restrict__ fc1w, const float* __restrict__ fc1b,
                const float* __restrict__ fc2w, const float* __restrict__ fc2b,
                float* __restrict__ out)
{
    // per-warp double-buffered broadcast of packed (h,h) values
    __shared__ ull s_h1[2][2][HID];   // [warpInBlock][buf][unit]
    __shared__ ull s_h2[2][2][HID];
    __shared__ float s_fc1w[(HID / 2) * HID];
    __shared__ float s_fc1b[HID / 2];
    __shared__ float s_fc2w[HID / 2];
    __shared__ float s_fc2b;

    const int tid = threadIdx.x;
    for (int i = tid; i < (HID / 2) * HID; i += blockDim.x) s_fc1w[i] = fc1w[i];
    if (tid < HID / 2) { s_fc1b[tid] = fc1b[tid]; s_fc2w[tid] = fc2w[tid]; }
    if (tid == 0) s_fc2b = fc2b[0];
    __syncthreads();

    const int lane = tid & 31;
    const int w    = tid >> 5;                 // warp in block (0/1)
    const int g    = lane >> 4;                // 0 -> (i,f), 1 -> (g,o)
    const int j    = lane & 15;                // hidden unit
    const int b    = blockIdx.x * 2 + w;       // batch element

    // gate rows in torch order i,f,g,o: pair rows (rlo, rlo+16)
    const int rlo = j + (g ? 2 * HID : 0);
    const int rhi = rlo + HID;

    // weights in registers, packed per gate-pair
    const ull wx  = pack2(Wih1[rlo], Wih1[rhi]);
    const ull b1p = pack2(bih1[rlo] + bhh1[rlo], bih1[rhi] + bhh1[rhi]);
    const ull b2p = pack2(bih2[rlo] + bhh2[rlo], bih2[rhi] + bhh2[rhi]);

    ull w1[HID], w2i[HID], w2h[HID];
#pragma unroll
    for (int k = 0; k < HID; ++k) {
        w1[k]  = pack2(Whh1[rlo * HID + k], Whh1[rhi * HID + k]);
        w2i[k] = pack2(Wih2[rlo * HID + k], Wih2[rhi * HID + k]);
        w2h[k] = pack2(Whh2[rlo * HID + k], Whh2[rhi * HID + k]);
    }

    const ull zero2 = pack2(0.f, 0.f);

    // carried state
    float c1 = 0.f, c2 = 0.f, o_head = 0.f;
    ull p1  = b1p;   // b1 + Whh1 @ h1_prev   (h1_prev = 0 initially)
    ull p2h = b2p;   // b2 + Whh2 @ h2_prev

    const float* xrow = x + (size_t)b * SEQT;
    float* orow = out + (size_t)b * NOUT;
    float xt = xrow[0];

    int buf = 0;
#pragma unroll 2
    for (int t = 0; t < SEQT + FUT; ++t) {
        const float inp = (t < SEQT) ? xt : o_head;
        xt = xrow[(t + 1) & (SEQT - 1)];

        // ---- layer 1: finish gates (recurrent part pre-accumulated in p1) ----
        ull a1 = fma2(wx, pack2(inp, inp), p1);
        float u, v;
        unpack2(a1, u, v);
        float au = g ? tanh_ap(u) : sigm(u);   // g0: sig(i)   g1: tanh(g)
        float av = sigm(v);                    // g0: sig(f)   g1: sig(o)
        float ru = __shfl_xor_sync(0xffffffffu, au, 16);
        float rv = __shfl_xor_sync(0xffffffffu, av, 16);
        const float si1 = g ? ru : au, sf1 = g ? rv : av;
        const float tg1 = g ? au : ru, so1 = g ? av : rv;
        c1 = fmaf(sf1, c1, si1 * tg1);
        const float h1 = so1 * tanh_ap(c1);

        // ---- broadcast h1 (packed) ----
        if (!g) s_h1[w][buf][j] = pack2(h1, h1);
        __syncwarp();

        // layer-2 input part + pre-accumulate next-step Whh1 @ h1
        ull a2a = p2h, a2b = zero2;
        ull p1a = b1p, p1b = zero2;
        const ulonglong2* q1 = (const ulonglong2*)s_h1[w][buf];
#pragma unroll
        for (int m = 0; m < HID / 2; ++m) {
            const ulonglong2 q = q1[m];
            a2a = fma2(w2i[2 * m],     q.x, a2a);
            a2b = fma2(w2i[2 * m + 1], q.y, a2b);
            p1a = fma2(w1[2 * m],      q.x, p1a);
            p1b = fma2(w1[2 * m + 1],  q.y, p1b);
        }
        const ull a2 = add2(a2a, a2b);
        p1 = add2(p1a, p1b);

        // ---- layer 2 activations ----
        unpack2(a2, u, v);
        au = g ? tanh_ap(u) : sigm(u);
        av = sigm(v);
        ru = __shfl_xor_sync(0xffffffffu, au, 16);
        rv = __shfl_xor_sync(0xffffffffu, av, 16);
        const float si2 = g ? ru : au, sf2 = g ? rv : av;
        const float tg2 = g ? au : ru, so2 = g ? av : rv;
        c2 = fmaf(sf2, c2, si2 * tg2);
        const float h2 = so2 * tanh_ap(c2);

        // ---- broadcast h2 (packed), pre-accumulate next-step Whh2 @ h2 ----
        if (!g) s_h2[w][buf][j] = pack2(h2, h2);
        __syncwarp();

        ull p2a = b2p, p2b = zero2;
        const ulonglong2* q2 = (const ulonglong2*)s_h2[w][buf];
#pragma unroll
        for (int m = 0; m < HID / 2; ++m) {
            const ulonglong2 q = q2[m];
            p2a = fma2(w2h[2 * m],     q.x, p2a);
            p2b = fma2(w2h[2 * m + 1], q.y, p2b);
        }
        p2h = add2(p2a, p2b);

        // ---- head (last teacher step + future steps only) ----
        if (t >= SEQT - 1) {
            const float* h2f = (const float*)s_h2[w][buf];  // packed: stride 2 floats
            const int jj = lane & 7;
            float acc = s_fc1b[jj];
#pragma unroll
            for (int k = 0; k < HID; ++k)
                acc = fmaf(s_fc1w[jj * HID + k], h2f[2 * k], acc);
            acc = (acc >= 0.f) ? acc : 0.2f * acc;          // LeakyReLU(0.2)
            float p = s_fc2w[jj] * acc;
            p += __shfl_xor_sync(0xffffffffu, p, 4);
            p += __shfl_xor_sync(0xffffffffu, p, 2);
            p += __shfl_xor_sync(0xffffffffu, p, 1);
            o_head = p + s_fc2b;
            if (lane == 0) orow[t - (SEQT - 1)] = o_head;
        }

        buf ^= 1;
    }
}

extern "C" void kernel_launch(void* const* d_in, const int* in_sizes, int n_in,
                              void* d_out, int out_size)
{
    const float* x    = (const float*)d_in[0];
    const float* Wih1 = (const float*)d_in[1];
    const float* Whh1 = (const float*)d_in[2];
    const float* bih1 = (const float*)d_in[3];
    const float* bhh1 = (const float*)d_in[4];
    const float* Wih2 = (const float*)d_in[5];
    const float* Whh2 = (const float*)d_in[6];
    const float* bih2 = (const float*)d_in[7];
    const float* bhh2 = (const float*)d_in[8];
    const float* fc1w = (const float*)d_in[9];
    const float* fc1b = (const float*)d_in[10];
    const float* fc2w = (const float*)d_in[11];
    const float* fc2b = (const float*)d_in[12];
    float* out = (float*)d_out;

    // 64 threads = 2 warps = 2 batch elements per block
    lstm_net_kernel<<<BATCH / 2, 64>>>(x, Wih1, Whh1, bih1, bhh1,
                                       Wih2, Whh2, bih2, bhh2,
                                       fc1w, fc1b, fc2w, fc2b, out);
}

// round 4
// speedup vs baseline: 1.2085x; 1.2085x over previous
#include <cuda_runtime.h>
#include <cstdint>

#define HID   16
#define BATCH 2048
#define SEQT  2048
#define FUT   32
#define NOUT  (FUT + 1)

typedef unsigned long long ull;

// ---------- packed f32x2 helpers (sm_103a) ----------
__device__ __forceinline__ ull pack2(float lo, float hi) {
    ull r;
    asm("mov.b64 %0, {%1, %2};" : "=l"(r) : "f"(lo), "f"(hi));
    return r;
}
__device__ __forceinline__ void unpack2(ull v, float& lo, float& hi) {
    asm("mov.b64 {%0, %1}, %2;" : "=f"(lo), "=f"(hi) : "l"(v));
}
__device__ __forceinline__ ull fma2(ull a, ull b, ull c) {
    ull d;
    asm("fma.rn.f32x2 %0, %1, %2, %3;" : "=l"(d) : "l"(a), "l"(b), "l"(c));
    return d;
}

// ---------- fast activations ----------
__device__ __forceinline__ float tanh_ap(float x) {
    float y;
    asm("tanh.approx.f32 %0, %1;" : "=f"(y) : "f"(x));
    return y;
}
__device__ __forceinline__ float sigm(float x) {
    return fmaf(0.5f, tanh_ap(0.5f * x), 0.5f);
}

// One warp = one batch element.
// lane = h*16 + j. Lane owns gate rows rA = j + 16h (i_j or f_j)
// and rB = rA + 32 (g_j or o_j). Weights packed along k (k-pairs).
__global__ void __launch_bounds__(64, 7)
lstm_net_kernel(const float* __restrict__ x,
                const float* __restrict__ Wih1, const float* __restrict__ Whh1,
                const float* __restrict__ bih1, const float* __restrict__ bhh1,
                const float* __restrict__ Wih2, const float* __restrict__ Whh2,
                const float* __restrict__ bih2, const float* __restrict__ bhh2,
                const float* __restrict__ fc1w, const float* __restrict__ fc1b,
                const float* __restrict__ fc2w, const float* __restrict__ fc2b,
                float* __restrict__ out)
{
    __shared__ float s_fc1w[(HID / 2) * HID];
    __shared__ float s_fc1b[HID / 2];
    __shared__ float s_fc2w[HID / 2];
    __shared__ float s_fc2b;

    const int tid = threadIdx.x;
    for (int i = tid; i < (HID / 2) * HID; i += blockDim.x) s_fc1w[i] = fc1w[i];
    if (tid < HID / 2) { s_fc1b[tid] = fc1b[tid]; s_fc2w[tid] = fc2w[tid]; }
    if (tid == 0) s_fc2b = fc2b[0];
    __syncthreads();

    const int lane = tid & 31;
    const int h    = lane >> 4;           // 0: rows (i,g)   1: rows (f,o)
    const int j    = lane & 15;           // hidden unit
    const int hb   = lane & 16;           // same-half shuffle base
    const int b    = blockIdx.x * 2 + (tid >> 5);

    const int rA = j + (h << 4);          // i_j (h=0) or f_j (h=1)
    const int rB = rA + 32;               // g_j (h=0) or o_j (h=1)

    // scalar input weights + biases
    const float wxA = Wih1[rA], wxB = Wih1[rB];
    const float b1A = bih1[rA] + bhh1[rA], b1B = bih1[rB] + bhh1[rB];
    const float b2A = bih2[rA] + bhh2[rA], b2B = bih2[rB] + bhh2[rB];

    // k-pair packed weights: 6 arrays x 8 ull = 96 regs
    ull w1A[8], w1B[8], w2iA[8], w2iB[8], w2hA[8], w2hB[8];
#pragma unroll
    for (int m = 0; m < 8; ++m) {
        w1A[m]  = pack2(Whh1[rA * HID + 2 * m], Whh1[rA * HID + 2 * m + 1]);
        w1B[m]  = pack2(Whh1[rB * HID + 2 * m], Whh1[rB * HID + 2 * m + 1]);
        w2iA[m] = pack2(Wih2[rA * HID + 2 * m], Wih2[rA * HID + 2 * m + 1]);
        w2iB[m] = pack2(Wih2[rB * HID + 2 * m], Wih2[rB * HID + 2 * m + 1]);
        w2hA[m] = pack2(Whh2[rA * HID + 2 * m], Whh2[rA * HID + 2 * m + 1]);
        w2hB[m] = pack2(Whh2[rB * HID + 2 * m], Whh2[rB * HID + 2 * m + 1]);
    }

    // carried state. pXA/pXB hold bias + Whh @ h_prev for this lane's 2 rows.
    float c1 = 0.f, c2 = 0.f, o_head = 0.f;
    ull p1A = pack2(b1A, 0.f), p1B = pack2(b1B, 0.f);
    ull p2A = pack2(b2A, 0.f), p2B = pack2(b2B, 0.f);

    const float* xrow = x + (size_t)b * SEQT;
    float* orow = out + (size_t)b * NOUT;
    float xt = xrow[0];

#pragma unroll 1
    for (int t = 0; t < SEQT + FUT; ++t) {
        const float inp = (t < SEQT) ? xt : o_head;
        xt = xrow[(t + 1) & (SEQT - 1)];

        // ======== layer 1 gates (recurrent part pre-accumulated) ========
        float lo, hi, uA, uB;
        unpack2(p1A, lo, hi); uA = fmaf(wxA, inp, lo + hi);
        unpack2(p1B, lo, hi); uB = fmaf(wxB, inp, lo + hi);

        // vA: sigmoid for both halves (i or f). vB: tanh (g) for h=0, sigmoid (o) for h=1.
        const float vA = sigm(uA);
        float tb = tanh_ap(h ? 0.5f * uB : uB);
        const float vB = h ? fmaf(0.5f, tb, 0.5f) : tb;
        const float xA = __shfl_xor_sync(0xffffffffu, vA, 16);
        const float xB = __shfl_xor_sync(0xffffffffu, vB, 16);
        const float iv = h ? xA : vA, fv = h ? vA : xA;
        const float gv = h ? xB : vB, ov = h ? vB : xB;
        c1 = fmaf(fv, c1, iv * gv);
        const float h1 = ov * tanh_ap(c1);

        // ==== broadcast h1 via shfl pairs; feed Wih2 (this step) + Whh1 (next) ====
        ull a2A = p2A, a2B = p2B;                 // b2 + Whh2 @ h2_prev
        ull n1A = pack2(b1A, 0.f), n1B = pack2(b1B, 0.f);
#pragma unroll
        for (int m = 0; m < 8; ++m) {
            const float e0 = __shfl_sync(0xffffffffu, h1, hb | (2 * m));
            const float e1 = __shfl_sync(0xffffffffu, h1, hb | (2 * m + 1));
            const ull hp = pack2(e0, e1);
            a2A = fma2(w2iA[m], hp, a2A);
            a2B = fma2(w2iB[m], hp, a2B);
            n1A = fma2(w1A[m], hp, n1A);
            n1B = fma2(w1B[m], hp, n1B);
        }
        p1A = n1A; p1B = n1B;

        // ======== layer 2 gates ========
        unpack2(a2A, lo, hi); uA = lo + hi;
        unpack2(a2B, lo, hi); uB = lo + hi;
        const float vA2 = sigm(uA);
        tb = tanh_ap(h ? 0.5f * uB : uB);
        const float vB2 = h ? fmaf(0.5f, tb, 0.5f) : tb;
        const float yA = __shfl_xor_sync(0xffffffffu, vA2, 16);
        const float yB = __shfl_xor_sync(0xffffffffu, vB2, 16);
        const float iv2 = h ? yA : vA2, fv2 = h ? vA2 : yA;
        const float gv2 = h ? yB : vB2, ov2 = h ? vB2 : yB;
        c2 = fmaf(fv2, c2, iv2 * gv2);
        const float h2 = ov2 * tanh_ap(c2);

        // ==== broadcast h2; pre-accumulate Whh2 @ h2 for next step ====
        ull n2A = pack2(b2A, 0.f), n2B = pack2(b2B, 0.f);
#pragma unroll
        for (int m = 0; m < 8; ++m) {
            const float e0 = __shfl_sync(0xffffffffu, h2, hb | (2 * m));
            const float e1 = __shfl_sync(0xffffffffu, h2, hb | (2 * m + 1));
            const ull hp = pack2(e0, e1);
            n2A = fma2(w2hA[m], hp, n2A);
            n2B = fma2(w2hB[m], hp, n2B);
        }
        p2A = n2A; p2B = n2B;

        // ======== head (last teacher step + future steps only) ========
        if (t >= SEQT - 1) {
            const int jj = lane & 7;
            float acc = s_fc1b[jj];
#pragma unroll
            for (int k = 0; k < HID; ++k) {
                const float hk = __shfl_sync(0xffffffffu, h2, hb | k);
                acc = fmaf(s_fc1w[jj * HID + k], hk, acc);
            }
            acc = (acc >= 0.f) ? acc : 0.2f * acc;      // LeakyReLU(0.2)
            float p = s_fc2w[jj] * acc;
            p += __shfl_xor_sync(0xffffffffu, p, 4);
            p += __shfl_xor_sync(0xffffffffu, p, 2);
            p += __shfl_xor_sync(0xffffffffu, p, 1);
            o_head = p + s_fc2b;                        // all lanes hold result
            if (lane == 0) orow[t - (SEQT - 1)] = o_head;
        }
    }
}

extern "C" void kernel_launch(void* const* d_in, const int* in_sizes, int n_in,
                              void* d_out, int out_size)
{
    const float* x    = (const float*)d_in[0];
    const float* Wih1 = (const float*)d_in[1];
    const float* Whh1 = (const float*)d_in[2];
    const float* bih1 = (const float*)d_in[3];
    const float* bhh1 = (const float*)d_in[4];
    const float* Wih2 = (const float*)d_in[5];
    const float* Whh2 = (const float*)d_in[6];
    const float* bih2 = (const float*)d_in[7];
    const float* bhh2 = (const float*)d_in[8];
    const float* fc1w = (const float*)d_in[9];
    const float* fc1b = (const float*)d_in[10];
    const float* fc2w = (const float*)d_in[11];
    const float* fc2b = (const float*)d_in[12];
    float* out = (float*)d_out;

    // 64 threads = 2 warps = 2 batch elements per block; 1024 blocks, one wave
    lstm_net_kernel<<<BATCH / 2, 64>>>(x, Wih1, Whh1, bih1, bhh1,
                                       Wih2, Whh2, bih2, bhh2,
                                       fc1w, fc1b, fc2w, fc2b, out);
}

// round 5
// speedup vs baseline: 1.5929x; 1.3180x over previous
#include <cuda_runtime.h>
#include <cstdint>

#define HID   16
#define BATCH 2048
#define SEQT  2048
#define FUT   32
#define NOUT  (FUT + 1)

typedef unsigned long long ull;

// ---------- packed f32x2 helpers (sm_103a) ----------
__device__ __forceinline__ ull pack2(float lo, float hi) {
    ull r;
    asm("mov.b64 %0, {%1, %2};" : "=l"(r) : "f"(lo), "f"(hi));
    return r;
}
__device__ __forceinline__ void unpack2(ull v, float& lo, float& hi) {
    asm("mov.b64 {%0, %1}, %2;" : "=f"(lo), "=f"(hi) : "l"(v));
}
__device__ __forceinline__ ull fma2(ull a, ull b, ull c) {
    ull d;
    asm("fma.rn.f32x2 %0, %1, %2, %3;" : "=l"(d) : "l"(a), "l"(b), "l"(c));
    return d;
}
__device__ __forceinline__ ull add2(ull a, ull b) {
    ull d;
    asm("add.rn.f32x2 %0, %1, %2;" : "=l"(d) : "l"(a), "l"(b));
    return d;
}
__device__ __forceinline__ float hadd2(ull v) {
    float lo, hi; unpack2(v, lo, hi); return lo + hi;
}

// ---------- fast activations ----------
__device__ __forceinline__ float tanh_ap(float x) {
    float y;
    asm("tanh.approx.f32 %0, %1;" : "=f"(y) : "f"(x));
    return y;
}
__device__ __forceinline__ float sigm(float x) {
    return fmaf(0.5f, tanh_ap(0.5f * x), 0.5f);
}

// One warp = TWO batch elements. lane = half*16 + j.
// Lane owns ALL FOUR gate rows of hidden unit j for its element:
//   r0=j (i), r1=j+16 (f), r2=j+32 (g), r3=j+48 (o).
// Weights packed along k (k-pairs) so each shfl-pair broadcast feeds 8-12 fma2.
// Recurrent matvecs for step t+1 are pre-accumulated at step t (h is broadcast once).
__global__ void __launch_bounds__(128, 2)
lstm_net_kernel(const float* __restrict__ x,
                const float* __restrict__ Wih1, const float* __restrict__ Whh1,
                const float* __restrict__ bih1, const float* __restrict__ bhh1,
                const float* __restrict__ Wih2, const float* __restrict__ Whh2,
                const float* __restrict__ bih2, const float* __restrict__ bhh2,
                const float* __restrict__ fc1w, const float* __restrict__ fc1b,
                const float* __restrict__ fc2w, const float* __restrict__ fc2b,
                float* __restrict__ out)
{
    __shared__ float s_fc1w[(HID / 2) * HID];
    __shared__ float s_fc1b[HID / 2];
    __shared__ float s_fc2w[HID / 2];
    __shared__ float s_fc2b;

    const int tid = threadIdx.x;
    if (tid < (HID / 2) * HID) s_fc1w[tid] = fc1w[tid];
    if (tid < HID / 2) { s_fc1b[tid] = fc1b[tid]; s_fc2w[tid] = fc2w[tid]; }
    if (tid == 0) s_fc2b = fc2b[0];
    __syncthreads();

    const int lane = tid & 31;
    const int j    = lane & 15;                 // hidden unit
    const int hb   = lane & 16;                 // half-warp shuffle base
    const int b    = (blockIdx.x * 4 + (tid >> 5)) * 2 + (lane >> 4);

    const int r0 = j, r1 = j + HID, r2 = j + 2 * HID, r3 = j + 3 * HID;

    // input weights + fused biases (scalars)
    const float wxi = Wih1[r0], wxf = Wih1[r1], wxg = Wih1[r2], wxo = Wih1[r3];
    const float b1i = bih1[r0] + bhh1[r0], b1f = bih1[r1] + bhh1[r1];
    const float b1g = bih1[r2] + bhh1[r2], b1o = bih1[r3] + bhh1[r3];
    const float b2i = bih2[r0] + bhh2[r0], b2f = bih2[r1] + bhh2[r1];
    const float b2g = bih2[r2] + bhh2[r2], b2o = bih2[r3] + bhh2[r3];

    // k-pair packed weights: 12 arrays x 8 ull = 192 regs
    ull w1i_[8], w1f_[8], w1g_[8], w1o_[8];
    ull w2ii[8], w2if[8], w2ig[8], w2io[8];
    ull w2hi[8], w2hf[8], w2hg[8], w2ho[8];
#pragma unroll
    for (int m = 0; m < 8; ++m) {
        w1i_[m] = pack2(Whh1[r0 * HID + 2 * m], Whh1[r0 * HID + 2 * m + 1]);
        w1f_[m] = pack2(Whh1[r1 * HID + 2 * m], Whh1[r1 * HID + 2 * m + 1]);
        w1g_[m] = pack2(Whh1[r2 * HID + 2 * m], Whh1[r2 * HID + 2 * m + 1]);
        w1o_[m] = pack2(Whh1[r3 * HID + 2 * m], Whh1[r3 * HID + 2 * m + 1]);
        w2ii[m] = pack2(Wih2[r0 * HID + 2 * m], Wih2[r0 * HID + 2 * m + 1]);
        w2if[m] = pack2(Wih2[r1 * HID + 2 * m], Wih2[r1 * HID + 2 * m + 1]);
        w2ig[m] = pack2(Wih2[r2 * HID + 2 * m], Wih2[r2 * HID + 2 * m + 1]);
        w2io[m] = pack2(Wih2[r3 * HID + 2 * m], Wih2[r3 * HID + 2 * m + 1]);
        w2hi[m] = pack2(Whh2[r0 * HID + 2 * m], Whh2[r0 * HID + 2 * m + 1]);
        w2hf[m] = pack2(Whh2[r1 * HID + 2 * m], Whh2[r1 * HID + 2 * m + 1]);
        w2hg[m] = pack2(Whh2[r2 * HID + 2 * m], Whh2[r2 * HID + 2 * m + 1]);
        w2ho[m] = pack2(Whh2[r3 * HID + 2 * m], Whh2[r3 * HID + 2 * m + 1]);
    }

    const ull zero2 = pack2(0.f, 0.f);

    // carried state
    float c1 = 0.f, c2 = 0.f, o_head = 0.f;
    // p1* = b1 + Whh1 @ h1_prev (packed, horizontal sum pending)
    ull p1i = pack2(b1i, 0.f), p1f = pack2(b1f, 0.f);
    ull p1g = pack2(b1g, 0.f), p1o = pack2(b1o, 0.f);
    // p2* = Whh2 @ h2_prev (bias lives in the a2 init)
    ull p2i = zero2, p2f = zero2, p2g = zero2, p2o = zero2;

    const float* xrow = x + (size_t)b * SEQT;
    float* orow = out + (size_t)b * NOUT;
    float xt = xrow[0];

#pragma unroll 2
    for (int t = 0; t < SEQT + FUT; ++t) {
        const float inp = (t < SEQT) ? xt : o_head;
        xt = xrow[(t + 1) & (SEQT - 1)];

        // ======== layer 1 gates (recurrent part pre-accumulated in p1*) ========
        const float ui = fmaf(wxi, inp, hadd2(p1i));
        const float uf = fmaf(wxf, inp, hadd2(p1f));
        const float ug = fmaf(wxg, inp, hadd2(p1g));
        const float uo = fmaf(wxo, inp, hadd2(p1o));
        const float i1 = sigm(ui), f1 = sigm(uf);
        const float g1 = tanh_ap(ug), o1 = sigm(uo);
        c1 = fmaf(f1, c1, i1 * g1);
        const float h1 = o1 * tanh_ap(c1);

        // ==== broadcast h1 once: feeds Wih2 (this step) + Whh1 (next step) ====
        ull a2i = pack2(b2i, 0.f), a2f = pack2(b2f, 0.f);
        ull a2g = pack2(b2g, 0.f), a2o = pack2(b2o, 0.f);
        ull n1i = pack2(b1i, 0.f), n1f = pack2(b1f, 0.f);
        ull n1g = pack2(b1g, 0.f), n1o = pack2(b1o, 0.f);
#pragma unroll
        for (int m = 0; m < 8; ++m) {
            const float e0 = __shfl_sync(0xffffffffu, h1, hb | (2 * m));
            const float e1 = __shfl_sync(0xffffffffu, h1, hb | (2 * m + 1));
            const ull hp = pack2(e0, e1);
            a2i = fma2(w2ii[m], hp, a2i);
            a2f = fma2(w2if[m], hp, a2f);
            a2g = fma2(w2ig[m], hp, a2g);
            a2o = fma2(w2io[m], hp, a2o);
            n1i = fma2(w1i_[m], hp, n1i);
            n1f = fma2(w1f_[m], hp, n1f);
            n1g = fma2(w1g_[m], hp, n1g);
            n1o = fma2(w1o_[m], hp, n1o);
        }
        p1i = n1i; p1f = n1f; p1g = n1g; p1o = n1o;

        // ======== layer 2 gates ========
        const float vi = hadd2(add2(a2i, p2i));
        const float vf = hadd2(add2(a2f, p2f));
        const float vg = hadd2(add2(a2g, p2g));
        const float vo = hadd2(add2(a2o, p2o));
        const float i2 = sigm(vi), f2 = sigm(vf);
        const float g2 = tanh_ap(vg), o2 = sigm(vo);
        c2 = fmaf(f2, c2, i2 * g2);
        const float h2 = o2 * tanh_ap(c2);

        // ==== broadcast h2 once: pre-accumulate Whh2 @ h2 for next step ====
        ull n2i = zero2, n2f = zero2, n2g = zero2, n2o = zero2;
#pragma unroll
        for (int m = 0; m < 8; ++m) {
            const float e0 = __shfl_sync(0xffffffffu, h2, hb | (2 * m));
            const float e1 = __shfl_sync(0xffffffffu, h2, hb | (2 * m + 1));
            const ull hp = pack2(e0, e1);
            n2i = fma2(w2hi[m], hp, n2i);
            n2f = fma2(w2hf[m], hp, n2f);
            n2g = fma2(w2hg[m], hp, n2g);
            n2o = fma2(w2ho[m], hp, n2o);
        }
        p2i = n2i; p2f = n2f; p2g = n2g; p2o = n2o;

        // ======== head (last teacher step + future steps only) ========
        if (t >= SEQT - 1) {
            const int jj = j & 7;
            float acc = s_fc1b[jj];
#pragma unroll
            for (int k = 0; k < HID; ++k) {
                const float hk = __shfl_sync(0xffffffffu, h2, hb | k);
                acc = fmaf(s_fc1w[jj * HID + k], hk, acc);
            }
            acc = (acc >= 0.f) ? acc : 0.2f * acc;      // LeakyReLU(0.2)
            float p = (j < 8) ? s_fc2w[jj] * acc : 0.f;
            p += __shfl_xor_sync(0xffffffffu, p, 8);
            p += __shfl_xor_sync(0xffffffffu, p, 4);
            p += __shfl_xor_sync(0xffffffffu, p, 2);
            p += __shfl_xor_sync(0xffffffffu, p, 1);
            o_head = p + s_fc2b;
            if (j == 0) orow[t - (SEQT - 1)] = o_head;
        }
    }
}

extern "C" void kernel_launch(void* const* d_in, const int* in_sizes, int n_in,
                              void* d_out, int out_size)
{
    const float* x    = (const float*)d_in[0];
    const float* Wih1 = (const float*)d_in[1];
    const float* Whh1 = (const float*)d_in[2];
    const float* bih1 = (const float*)d_in[3];
    const float* bhh1 = (const float*)d_in[4];
    const float* Wih2 = (const float*)d_in[5];
    const float* Whh2 = (const float*)d_in[6];
    const float* bih2 = (const float*)d_in[7];
    const float* bhh2 = (const float*)d_in[8];
    const float* fc1w = (const float*)d_in[9];
    const float* fc1b = (const float*)d_in[10];
    const float* fc2w = (const float*)d_in[11];
    const float* fc2b = (const float*)d_in[12];
    float* out = (float*)d_out;

    // 128 threads = 4 warps = 8 batch elements per block -> 256 blocks
    lstm_net_kernel<<<BATCH / 8, 128>>>(x, Wih1, Whh1, bih1, bhh1,
                                        Wih2, Whh2, bih2, bhh2,
                                        fc1w, fc1b, fc2w, fc2b, out);
}

// round 6
// speedup vs baseline: 1.7980x; 1.1288x over previous
#include <cuda_runtime.h>
#include <cstdint>

#define HID   16
#define BATCH 2048
#define SEQT  2048
#define FUT   32
#define NOUT  (FUT + 1)
#define WPB   4            // warps per block

typedef unsigned long long ull;

// ---------- packed f32x2 helpers (sm_103a) ----------
__device__ __forceinline__ ull pack2(float lo, float hi) {
    ull r;
    asm("mov.b64 %0, {%1, %2};" : "=l"(r) : "f"(lo), "f"(hi));
    return r;
}
__device__ __forceinline__ void unpack2(ull v, float& lo, float& hi) {
    asm("mov.b64 {%0, %1}, %2;" : "=f"(lo), "=f"(hi) : "l"(v));
}
__device__ __forceinline__ ull fma2(ull a, ull b, ull c) {
    ull d;
    asm("fma.rn.f32x2 %0, %1, %2, %3;" : "=l"(d) : "l"(a), "l"(b), "l"(c));
    return d;
}
__device__ __forceinline__ ull add2(ull a, ull b) {
    ull d;
    asm("add.rn.f32x2 %0, %1, %2;" : "=l"(d) : "l"(a), "l"(b));
    return d;
}
__device__ __forceinline__ float hadd2(ull v) {
    float lo, hi; unpack2(v, lo, hi); return lo + hi;
}

// ---------- fast activations ----------
__device__ __forceinline__ float tanh_ap(float x) {
    float y;
    asm("tanh.approx.f32 %0, %1;" : "=f"(y) : "f"(x));
    return y;
}
__device__ __forceinline__ float sigm(float x) {
    return fmaf(0.5f, tanh_ap(0.5f * x), 0.5f);
}

// One warp = TWO batch elements (lane = e*16 + j). Lane owns all 4 gate rows of
// unit j for its element. i/f rows' weights in registers; g/o rows' layer-2
// weights in shared (off critical path). Hidden-state broadcast via smem:
// STS.32 + LDS.128, the float4 reinterpreting directly as packed f32x2 pairs.
// Whh@h for step t+1 pre-accumulated at step t (single broadcast per h).
__global__ void __launch_bounds__(128, 2)
lstm_net_kernel(const float* __restrict__ x,
                const float* __restrict__ Wih1, const float* __restrict__ Whh1,
                const float* __restrict__ bih1, const float* __restrict__ bhh1,
                const float* __restrict__ Wih2, const float* __restrict__ Whh2,
                const float* __restrict__ bih2, const float* __restrict__ bhh2,
                const float* __restrict__ fc1w, const float* __restrict__ fc1b,
                const float* __restrict__ fc2w, const float* __restrict__ fc2b,
                float* __restrict__ out)
{
    // g/o-row weights for layer-2 matvecs, k-pair packed: [m][j] = {g-row, o-row}
    __shared__ ulonglong2 s_w2igo[8][HID];   // Wih2 rows 32..63
    __shared__ ulonglong2 s_w2hgo[8][HID];   // Whh2 rows 32..63
    // hidden-state broadcast buffers: [warp][elem][16 floats]
    __shared__ float4 s_h1[WPB][2][4];
    __shared__ float4 s_h2[WPB][2][4];
    // FC head
    __shared__ float s_fc1w[(HID / 2) * HID];
    __shared__ float s_fc1b[HID / 2];
    __shared__ float s_fc2w[HID / 2];
    __shared__ float s_fc2b;

    const int tid = threadIdx.x;
    {
        const int m = tid >> 4, jj = tid & 15;   // 128 threads -> all (m,j)
        s_w2igo[m][jj] = make_ulonglong2(
            pack2(Wih2[(32 + jj) * HID + 2 * m], Wih2[(32 + jj) * HID + 2 * m + 1]),
            pack2(Wih2[(48 + jj) * HID + 2 * m], Wih2[(48 + jj) * HID + 2 * m + 1]));
        s_w2hgo[m][jj] = make_ulonglong2(
            pack2(Whh2[(32 + jj) * HID + 2 * m], Whh2[(32 + jj) * HID + 2 * m + 1]),
            pack2(Whh2[(48 + jj) * HID + 2 * m], Whh2[(48 + jj) * HID + 2 * m + 1]));
    }
    if (tid < (HID / 2) * HID) s_fc1w[tid] = fc1w[tid];
    if (tid < HID / 2) { s_fc1b[tid] = fc1b[tid]; s_fc2w[tid] = fc2w[tid]; }
    if (tid == 0) s_fc2b = fc2b[0];
    __syncthreads();

    const int lane = tid & 31;
    const int w    = tid >> 5;                  // warp in block
    const int e    = lane >> 4;                 // element half (0/1)
    const int j    = lane & 15;                 // hidden unit
    const int b    = (blockIdx.x * WPB + w) * 2 + e;

    const int r0 = j, r1 = j + HID, r2 = j + 2 * HID, r3 = j + 3 * HID;

    // input weights + fused biases
    const float wxi = Wih1[r0], wxf = Wih1[r1], wxg = Wih1[r2], wxo = Wih1[r3];
    const float b1i = bih1[r0] + bhh1[r0], b1f = bih1[r1] + bhh1[r1];
    const float b1g = bih1[r2] + bhh1[r2], b1o = bih1[r3] + bhh1[r3];
    const float b2i = bih2[r0] + bhh2[r0], b2f = bih2[r1] + bhh2[r1];
    const float b2g = bih2[r2] + bhh2[r2], b2o = bih2[r3] + bhh2[r3];

    // register-resident weights (k-pair packed): Whh1 all 4 rows (critical path),
    // Wih2/Whh2 i,f rows only. 64 ull = 128 regs.
    ull w1i_[8], w1f_[8], w1g_[8], w1o_[8];
    ull w2ii[8], w2if[8], w2hi[8], w2hf[8];
#pragma unroll
    for (int m = 0; m < 8; ++m) {
        w1i_[m] = pack2(Whh1[r0 * HID + 2 * m], Whh1[r0 * HID + 2 * m + 1]);
        w1f_[m] = pack2(Whh1[r1 * HID + 2 * m], Whh1[r1 * HID + 2 * m + 1]);
        w1g_[m] = pack2(Whh1[r2 * HID + 2 * m], Whh1[r2 * HID + 2 * m + 1]);
        w1o_[m] = pack2(Whh1[r3 * HID + 2 * m], Whh1[r3 * HID + 2 * m + 1]);
        w2ii[m] = pack2(Wih2[r0 * HID + 2 * m], Wih2[r0 * HID + 2 * m + 1]);
        w2if[m] = pack2(Wih2[r1 * HID + 2 * m], Wih2[r1 * HID + 2 * m + 1]);
        w2hi[m] = pack2(Whh2[r0 * HID + 2 * m], Whh2[r0 * HID + 2 * m + 1]);
        w2hf[m] = pack2(Whh2[r1 * HID + 2 * m], Whh2[r1 * HID + 2 * m + 1]);
    }

    // carried state. p1* = b1 + Whh1@h1_prev ; p2* = Whh2@h2_prev (b2 in a2 init)
    float c1 = 0.f, c2 = 0.f, o_head = 0.f;
    ull p1i = pack2(b1i, 0.f), p1f = pack2(b1f, 0.f);
    ull p1g = pack2(b1g, 0.f), p1o = pack2(b1o, 0.f);
    ull p2i = pack2(0.f, 0.f), p2f = p2i, p2g = p2i, p2o = p2i;

    float* s_h1me = (float*)&s_h1[w][e];
    float* s_h2me = (float*)&s_h2[w][e];
    const ulonglong2* s_h1rd = (const ulonglong2*)&s_h1[w][e];
    const ulonglong2* s_h2rd = (const ulonglong2*)&s_h2[w][e];

    const float* xrow = x + (size_t)b * SEQT;
    float* orow = out + (size_t)b * NOUT;
    float xt = xrow[0];

#pragma unroll 1
    for (int t = 0; t < SEQT + FUT; ++t) {
        const float inp = (t < SEQT) ? xt : o_head;
        xt = xrow[(t + 1) & (SEQT - 1)];

        // ======== layer 1 gates (recurrent part pre-accumulated in p1*) ========
        const float ui = fmaf(wxi, inp, hadd2(p1i));
        const float uf = fmaf(wxf, inp, hadd2(p1f));
        const float ug = fmaf(wxg, inp, hadd2(p1g));
        const float uo = fmaf(wxo, inp, hadd2(p1o));
        const float i1 = sigm(ui), f1 = sigm(uf);
        const float g1 = tanh_ap(ug), o1 = sigm(uo);
        c1 = fmaf(f1, c1, i1 * g1);
        const float h1 = o1 * tanh_ap(c1);

        // ==== broadcast h1 via smem; feeds Wih2 (now) + Whh1 (next step) ====
        s_h1me[j] = h1;
        __syncwarp();

        ull a2i = pack2(b2i, 0.f), a2f = pack2(b2f, 0.f);
        ull a2g = pack2(b2g, 0.f), a2o = pack2(b2o, 0.f);
        ull n1i = pack2(b1i, 0.f), n1f = pack2(b1f, 0.f);
        ull n1g = pack2(b1g, 0.f), n1o = pack2(b1o, 0.f);
#pragma unroll
        for (int q = 0; q < 4; ++q) {
            const ulonglong2 hq = s_h1rd[q];          // 2 packed h-pairs
            const ulonglong2 wg0 = s_w2igo[2 * q][j];
            const ulonglong2 wg1 = s_w2igo[2 * q + 1][j];
            a2i = fma2(w2ii[2 * q], hq.x, a2i);
            a2f = fma2(w2if[2 * q], hq.x, a2f);
            a2g = fma2(wg0.x, hq.x, a2g);
            a2o = fma2(wg0.y, hq.x, a2o);
            n1i = fma2(w1i_[2 * q], hq.x, n1i);
            n1f = fma2(w1f_[2 * q], hq.x, n1f);
            n1g = fma2(w1g_[2 * q], hq.x, n1g);
            n1o = fma2(w1o_[2 * q], hq.x, n1o);
            a2i = fma2(w2ii[2 * q + 1], hq.y, a2i);
            a2f = fma2(w2if[2 * q + 1], hq.y, a2f);
            a2g = fma2(wg1.x, hq.y, a2g);
            a2o = fma2(wg1.y, hq.y, a2o);
            n1i = fma2(w1i_[2 * q + 1], hq.y, n1i);
            n1f = fma2(w1f_[2 * q + 1], hq.y, n1f);
            n1g = fma2(w1g_[2 * q + 1], hq.y, n1g);
            n1o = fma2(w1o_[2 * q + 1], hq.y, n1o);
        }
        p1i = n1i; p1f = n1f; p1g = n1g; p1o = n1o;

        // ======== layer 2 gates ========
        const float vi = hadd2(add2(a2i, p2i));
        const float vf = hadd2(add2(a2f, p2f));
        const float vg = hadd2(add2(a2g, p2g));
        const float vo = hadd2(add2(a2o, p2o));
        const float i2 = sigm(vi), f2 = sigm(vf);
        const float g2 = tanh_ap(vg), o2 = sigm(vo);
        c2 = fmaf(f2, c2, i2 * g2);
        const float h2 = o2 * tanh_ap(c2);

        // ==== broadcast h2 via smem; pre-accumulate Whh2 @ h2 for next step ====
        s_h2me[j] = h2;
        __syncwarp();

        ull n2i = pack2(0.f, 0.f), n2f = n2i, n2g = n2i, n2o = n2i;
#pragma unroll
        for (int q = 0; q < 4; ++q) {
            const ulonglong2 hq = s_h2rd[q];
            const ulonglong2 wg0 = s_w2hgo[2 * q][j];
            const ulonglong2 wg1 = s_w2hgo[2 * q + 1][j];
            n2i = fma2(w2hi[2 * q], hq.x, n2i);
            n2f = fma2(w2hf[2 * q], hq.x, n2f);
            n2g = fma2(wg0.x, hq.x, n2g);
            n2o = fma2(wg0.y, hq.x, n2o);
            n2i = fma2(w2hi[2 * q + 1], hq.y, n2i);
            n2f = fma2(w2hf[2 * q + 1], hq.y, n2f);
            n2g = fma2(wg1.x, hq.y, n2g);
            n2o = fma2(wg1.y, hq.y, n2o);
        }
        p2i = n2i; p2f = n2f; p2g = n2g; p2o = n2o;

        // ======== head (last teacher step + future steps only) ========
        if (t >= SEQT - 1) {
            const int jj = j & 7;
            float acc = s_fc1b[jj];
            const float* h2f = s_h2me;
#pragma unroll
            for (int k = 0; k < HID; ++k)
                acc = fmaf(s_fc1w[jj * HID + k], h2f[k], acc);
            acc = (acc >= 0.f) ? acc : 0.2f * acc;      // LeakyReLU(0.2)
            float p = (j < 8) ? s_fc2w[jj] * acc : 0.f;
            p += __shfl_xor_sync(0xffffffffu, p, 8);
            p += __shfl_xor_sync(0xffffffffu, p, 4);
            p += __shfl_xor_sync(0xffffffffu, p, 2);
            p += __shfl_xor_sync(0xffffffffu, p, 1);
            o_head = p + s_fc2b;
            if (j == 0) orow[t - (SEQT - 1)] = o_head;
        }
    }
}

extern "C" void kernel_launch(void* const* d_in, const int* in_sizes, int n_in,
                              void* d_out, int out_size)
{
    const float* x    = (const float*)d_in[0];
    const float* Wih1 = (const float*)d_in[1];
    const float* Whh1 = (const float*)d_in[2];
    const float* bih1 = (const float*)d_in[3];
    const float* bhh1 = (const float*)d_in[4];
    const float* Wih2 = (const float*)d_in[5];
    const float* Whh2 = (const float*)d_in[6];
    const float* bih2 = (const float*)d_in[7];
    const float* bhh2 = (const float*)d_in[8];
    const float* fc1w = (const float*)d_in[9];
    const float* fc1b = (const float*)d_in[10];
    const float* fc2w = (const float*)d_in[11];
    const float* fc2b = (const float*)d_in[12];
    float* out = (float*)d_out;

    // 128 threads = 4 warps = 8 batch elements per block -> 256 blocks
    lstm_net_kernel<<<BATCH / 8, 128>>>(x, Wih1, Whh1, bih1, bhh1,
                                        Wih2, Whh2, bih2, bhh2,
                                        fc1w, fc1b, fc2w, fc2b, out);
}

// round 7
// speedup vs baseline: 1.9167x; 1.0660x over previous
#include <cuda_runtime.h>
#include <cstdint>

#define HID   16
#define BATCH 2048
#define SEQT  2048
#define FUT   32
#define NOUT  (FUT + 1)
#define WPB   8            // warps per block (8 warps -> 1 CTA/SM, 2 warps/SMSP uniform)

typedef unsigned long long ull;

// ---------- packed f32x2 helpers (sm_103a) ----------
__device__ __forceinline__ ull pack2(float lo, float hi) {
    ull r;
    asm("mov.b64 %0, {%1, %2};" : "=l"(r) : "f"(lo), "f"(hi));
    return r;
}
__device__ __forceinline__ void unpack2(ull v, float& lo, float& hi) {
    asm("mov.b64 {%0, %1}, %2;" : "=f"(lo), "=f"(hi) : "l"(v));
}
__device__ __forceinline__ ull fma2(ull a, ull b, ull c) {
    ull d;
    asm("fma.rn.f32x2 %0, %1, %2, %3;" : "=l"(d) : "l"(a), "l"(b), "l"(c));
    return d;
}
__device__ __forceinline__ ull add2(ull a, ull b) {
    ull d;
    asm("add.rn.f32x2 %0, %1, %2;" : "=l"(d) : "l"(a), "l"(b));
    return d;
}
__device__ __forceinline__ float hadd2(ull v) {
    float lo, hi; unpack2(v, lo, hi); return lo + hi;
}

// ---------- fast activations ----------
__device__ __forceinline__ float tanh_ap(float x) {
    float y;
    asm("tanh.approx.f32 %0, %1;" : "=f"(y) : "f"(x));
    return y;
}
__device__ __forceinline__ float sigm(float x) {
    return fmaf(0.5f, tanh_ap(0.5f * x), 0.5f);
}

// One warp = TWO batch elements (lane = e*16 + j). Lane owns all 4 gate rows of
// unit j for its element. i/f rows' weights in registers; g/o rows' layer-2
// weights in shared (off critical path). Hidden-state broadcast via smem:
// STS.32 + LDS.128, the float4 reinterpreting directly as packed f32x2 pairs.
// Whh@h for step t+1 pre-accumulated at step t (single broadcast per h).
// Grid: 128 CTAs x 8 warps -> one CTA per SM -> exactly 2 warps per SMSP
// everywhere (eliminates the 1-warp straggler SMs that paced earlier rounds).
__global__ void __launch_bounds__(32 * WPB, 1)
lstm_net_kernel(const float* __restrict__ x,
                const float* __restrict__ Wih1, const float* __restrict__ Whh1,
                const float* __restrict__ bih1, const float* __restrict__ bhh1,
                const float* __restrict__ Wih2, const float* __restrict__ Whh2,
                const float* __restrict__ bih2, const float* __restrict__ bhh2,
                const float* __restrict__ fc1w, const float* __restrict__ fc1b,
                const float* __restrict__ fc2w, const float* __restrict__ fc2b,
                float* __restrict__ out)
{
    // g/o-row weights for layer-2 matvecs, k-pair packed: [m][j] = {g-row, o-row}
    __shared__ ulonglong2 s_w2igo[8][HID];   // Wih2 rows 32..63
    __shared__ ulonglong2 s_w2hgo[8][HID];   // Whh2 rows 32..63
    // hidden-state broadcast buffers: [warp][elem][16 floats]
    __shared__ float4 s_h1[WPB][2][4];
    __shared__ float4 s_h2[WPB][2][4];
    // FC head
    __shared__ float s_fc1w[(HID / 2) * HID];
    __shared__ float s_fc1b[HID / 2];
    __shared__ float s_fc2w[HID / 2];
    __shared__ float s_fc2b;

    const int tid = threadIdx.x;
    if (tid < 128) {
        const int m = tid >> 4, jj = tid & 15;   // 128 threads cover all (m,j)
        s_w2igo[m][jj] = make_ulonglong2(
            pack2(Wih2[(32 + jj) * HID + 2 * m], Wih2[(32 + jj) * HID + 2 * m + 1]),
            pack2(Wih2[(48 + jj) * HID + 2 * m], Wih2[(48 + jj) * HID + 2 * m + 1]));
        s_w2hgo[m][jj] = make_ulonglong2(
            pack2(Whh2[(32 + jj) * HID + 2 * m], Whh2[(32 + jj) * HID + 2 * m + 1]),
            pack2(Whh2[(48 + jj) * HID + 2 * m], Whh2[(48 + jj) * HID + 2 * m + 1]));
    }
    if (tid < (HID / 2) * HID) s_fc1w[tid] = fc1w[tid];
    if (tid < HID / 2) { s_fc1b[tid] = fc1b[tid]; s_fc2w[tid] = fc2w[tid]; }
    if (tid == 0) s_fc2b = fc2b[0];
    __syncthreads();

    const int lane = tid & 31;
    const int w    = tid >> 5;                  // warp in block (0..7)
    const int e    = lane >> 4;                 // element half (0/1)
    const int j    = lane & 15;                 // hidden unit
    const int b    = (blockIdx.x * WPB + w) * 2 + e;

    const int r0 = j, r1 = j + HID, r2 = j + 2 * HID, r3 = j + 3 * HID;

    // input weights + fused biases
    const float wxi = Wih1[r0], wxf = Wih1[r1], wxg = Wih1[r2], wxo = Wih1[r3];
    const float b1i = bih1[r0] + bhh1[r0], b1f = bih1[r1] + bhh1[r1];
    const float b1g = bih1[r2] + bhh1[r2], b1o = bih1[r3] + bhh1[r3];
    const float b2i = bih2[r0] + bhh2[r0], b2f = bih2[r1] + bhh2[r1];
    const float b2g = bih2[r2] + bhh2[r2], b2o = bih2[r3] + bhh2[r3];

    // register-resident weights (k-pair packed): Whh1 all 4 rows (critical path),
    // Wih2/Whh2 i,f rows only. 64 ull = 128 regs.
    ull w1i_[8], w1f_[8], w1g_[8], w1o_[8];
    ull w2ii[8], w2if[8], w2hi[8], w2hf[8];
#pragma unroll
    for (int m = 0; m < 8; ++m) {
        w1i_[m] = pack2(Whh1[r0 * HID + 2 * m], Whh1[r0 * HID + 2 * m + 1]);
        w1f_[m] = pack2(Whh1[r1 * HID + 2 * m], Whh1[r1 * HID + 2 * m + 1]);
        w1g_[m] = pack2(Whh1[r2 * HID + 2 * m], Whh1[r2 * HID + 2 * m + 1]);
        w1o_[m] = pack2(Whh1[r3 * HID + 2 * m], Whh1[r3 * HID + 2 * m + 1]);
        w2ii[m] = pack2(Wih2[r0 * HID + 2 * m], Wih2[r0 * HID + 2 * m + 1]);
        w2if[m] = pack2(Wih2[r1 * HID + 2 * m], Wih2[r1 * HID + 2 * m + 1]);
        w2hi[m] = pack2(Whh2[r0 * HID + 2 * m], Whh2[r0 * HID + 2 * m + 1]);
        w2hf[m] = pack2(Whh2[r1 * HID + 2 * m], Whh2[r1 * HID + 2 * m + 1]);
    }

    // carried state. p1* = b1 + Whh1@h1_prev ; p2* = Whh2@h2_prev (b2 in a2 init)
    float c1 = 0.f, c2 = 0.f, o_head = 0.f;
    ull p1i = pack2(b1i, 0.f), p1f = pack2(b1f, 0.f);
    ull p1g = pack2(b1g, 0.f), p1o = pack2(b1o, 0.f);
    ull p2i = pack2(0.f, 0.f), p2f = p2i, p2g = p2i, p2o = p2i;

    float* s_h1me = (float*)&s_h1[w][e];
    float* s_h2me = (float*)&s_h2[w][e];
    const ulonglong2* s_h1rd = (const ulonglong2*)&s_h1[w][e];
    const ulonglong2* s_h2rd = (const ulonglong2*)&s_h2[w][e];

    const float* xrow = x + (size_t)b * SEQT;
    float* orow = out + (size_t)b * NOUT;
    float xt = xrow[0];

#pragma unroll 1
    for (int t = 0; t < SEQT + FUT; ++t) {
        const float inp = (t < SEQT) ? xt : o_head;
        xt = xrow[(t + 1) & (SEQT - 1)];

        // ======== layer 1 gates (recurrent part pre-accumulated in p1*) ========
        const float ui = fmaf(wxi, inp, hadd2(p1i));
        const float uf = fmaf(wxf, inp, hadd2(p1f));
        const float ug = fmaf(wxg, inp, hadd2(p1g));
        const float uo = fmaf(wxo, inp, hadd2(p1o));
        const float i1 = sigm(ui), f1 = sigm(uf);
        const float g1 = tanh_ap(ug), o1 = sigm(uo);
        c1 = fmaf(f1, c1, i1 * g1);
        const float h1 = o1 * tanh_ap(c1);

        // ==== broadcast h1 via smem; feeds Wih2 (now) + Whh1 (next step) ====
        s_h1me[j] = h1;
        __syncwarp();

        ull a2i = pack2(b2i, 0.f), a2f = pack2(b2f, 0.f);
        ull a2g = pack2(b2g, 0.f), a2o = pack2(b2o, 0.f);
        ull n1i = pack2(b1i, 0.f), n1f = pack2(b1f, 0.f);
        ull n1g = pack2(b1g, 0.f), n1o = pack2(b1o, 0.f);
#pragma unroll
        for (int q = 0; q < 4; ++q) {
            const ulonglong2 hq = s_h1rd[q];          // 2 packed h-pairs
            const ulonglong2 wg0 = s_w2igo[2 * q][j];
            const ulonglong2 wg1 = s_w2igo[2 * q + 1][j];
            a2i = fma2(w2ii[2 * q], hq.x, a2i);
            a2f = fma2(w2if[2 * q], hq.x, a2f);
            a2g = fma2(wg0.x, hq.x, a2g);
            a2o = fma2(wg0.y, hq.x, a2o);
            n1i = fma2(w1i_[2 * q], hq.x, n1i);
            n1f = fma2(w1f_[2 * q], hq.x, n1f);
            n1g = fma2(w1g_[2 * q], hq.x, n1g);
            n1o = fma2(w1o_[2 * q], hq.x, n1o);
            a2i = fma2(w2ii[2 * q + 1], hq.y, a2i);
            a2f = fma2(w2if[2 * q + 1], hq.y, a2f);
            a2g = fma2(wg1.x, hq.y, a2g);
            a2o = fma2(wg1.y, hq.y, a2o);
            n1i = fma2(w1i_[2 * q + 1], hq.y, n1i);
            n1f = fma2(w1f_[2 * q + 1], hq.y, n1f);
            n1g = fma2(w1g_[2 * q + 1], hq.y, n1g);
            n1o = fma2(w1o_[2 * q + 1], hq.y, n1o);
        }
        p1i = n1i; p1f = n1f; p1g = n1g; p1o = n1o;

        // ======== layer 2 gates ========
        const float vi = hadd2(add2(a2i, p2i));
        const float vf = hadd2(add2(a2f, p2f));
        const float vg = hadd2(add2(a2g, p2g));
        const float vo = hadd2(add2(a2o, p2o));
        const float i2 = sigm(vi), f2 = sigm(vf);
        const float g2 = tanh_ap(vg), o2 = sigm(vo);
        c2 = fmaf(f2, c2, i2 * g2);
        const float h2 = o2 * tanh_ap(c2);

        // ==== broadcast h2 via smem; pre-accumulate Whh2 @ h2 for next step ====
        s_h2me[j] = h2;
        __syncwarp();

        ull n2i = pack2(0.f, 0.f), n2f = n2i, n2g = n2i, n2o = n2i;
#pragma unroll
        for (int q = 0; q < 4; ++q) {
            const ulonglong2 hq = s_h2rd[q];
            const ulonglong2 wg0 = s_w2hgo[2 * q][j];
            const ulonglong2 wg1 = s_w2hgo[2 * q + 1][j];
            n2i = fma2(w2hi[2 * q], hq.x, n2i);
            n2f = fma2(w2hf[2 * q], hq.x, n2f);
            n2g = fma2(wg0.x, hq.x, n2g);
            n2o = fma2(wg0.y, hq.x, n2o);
            n2i = fma2(w2hi[2 * q + 1], hq.y, n2i);
            n2f = fma2(w2hf[2 * q + 1], hq.y, n2f);
            n2g = fma2(wg1.x, hq.y, n2g);
            n2o = fma2(wg1.y, hq.y, n2o);
        }
        p2i = n2i; p2f = n2f; p2g = n2g; p2o = n2o;

        // ======== head (last teacher step + future steps only) ========
        if (t >= SEQT - 1) {
            const int jj = j & 7;
            float acc = s_fc1b[jj];
            const float* h2f = s_h2me;
#pragma unroll
            for (int k = 0; k < HID; ++k)
                acc = fmaf(s_fc1w[jj * HID + k], h2f[k], acc);
            acc = (acc >= 0.f) ? acc : 0.2f * acc;      // LeakyReLU(0.2)
            float p = (j < 8) ? s_fc2w[jj] * acc : 0.f;
            p += __shfl_xor_sync(0xffffffffu, p, 8);
            p += __shfl_xor_sync(0xffffffffu, p, 4);
            p += __shfl_xor_sync(0xffffffffu, p, 2);
            p += __shfl_xor_sync(0xffffffffu, p, 1);
            o_head = p + s_fc2b;
            if (j == 0) orow[t - (SEQT - 1)] = o_head;
        }
    }
}

extern "C" void kernel_launch(void* const* d_in, const int* in_sizes, int n_in,
                              void* d_out, int out_size)
{
    const float* x    = (const float*)d_in[0];
    const float* Wih1 = (const float*)d_in[1];
    const float* Whh1 = (const float*)d_in[2];
    const float* bih1 = (const float*)d_in[3];
    const float* bhh1 = (const float*)d_in[4];
    const float* Wih2 = (const float*)d_in[5];
    const float* Whh2 = (const float*)d_in[6];
    const float* bih2 = (const float*)d_in[7];
    const float* bhh2 = (const float*)d_in[8];
    const float* fc1w = (const float*)d_in[9];
    const float* fc1b = (const float*)d_in[10];
    const float* fc2w = (const float*)d_in[11];
    const float* fc2b = (const float*)d_in[12];
    float* out = (float*)d_out;

    // 256 threads = 8 warps = 16 batch elements per block -> 128 blocks
    // (128 <= 148 SMs: one CTA per SM, exactly 2 warps per SMSP, uniform pace)
    lstm_net_kernel<<<BATCH / 16, 32 * WPB>>>(x, Wih1, Whh1, bih1, bhh1,
                                              Wih2, Whh2, bih2, bhh2,
                                              fc1w, fc1b, fc2w, fc2b, out);
}

// round 8
// speedup vs baseline: 1.9497x; 1.0172x over previous
#include <cuda_runtime.h>
#include <cstdint>

#define HID   16
#define BATCH 2048
#define SEQT  2048
#define FUT   32
#define NOUT  (FUT + 1)
#define WPB   8            // 8 warps/CTA, 128 CTAs -> 1 CTA/SM, 2 warps/SMSP uniform

typedef unsigned long long ull;

// ---------- packed f32x2 helpers (sm_103a) ----------
__device__ __forceinline__ ull pack2(float lo, float hi) {
    ull r;
    asm("mov.b64 %0, {%1, %2};" : "=l"(r) : "f"(lo), "f"(hi));
    return r;
}
__device__ __forceinline__ void unpack2(ull v, float& lo, float& hi) {
    asm("mov.b64 {%0, %1}, %2;" : "=f"(lo), "=f"(hi) : "l"(v));
}
__device__ __forceinline__ ull fma2(ull a, ull b, ull c) {
    ull d;
    asm("fma.rn.f32x2 %0, %1, %2, %3;" : "=l"(d) : "l"(a), "l"(b), "l"(c));
    return d;
}
__device__ __forceinline__ float hadd2(ull v) {
    float lo, hi; unpack2(v, lo, hi); return lo + hi;
}

// ---------- fast activations ----------
__device__ __forceinline__ float tanh_ap(float x) {
    float y;
    asm("tanh.approx.f32 %0, %1;" : "=f"(y) : "f"(x));
    return y;
}
__device__ __forceinline__ float sigm(float x) {
    return fmaf(0.5f, tanh_ap(0.5f * x), 0.5f);
}

// One warp = TWO batch elements (lane = e*16 + j); lane owns all 4 gate rows of
// unit j. 10 of 12 weight blocks live in REGISTERS (crossbar relief vs R6);
// only Whh2's g/o rows come from smem (in the slack-rich h2 loop).
// h broadcast via smem STS.32 + LDS.128 (float4 == two packed f32x2 operands).
// Whh@h for step t+1 pre-accumulated at step t, in place (no temp accumulators).
__global__ void __launch_bounds__(32 * WPB, 1)
lstm_net_kernel(const float* __restrict__ x,
                const float* __restrict__ Wih1, const float* __restrict__ Whh1,
                const float* __restrict__ bih1, const float* __restrict__ bhh1,
                const float* __restrict__ Wih2, const float* __restrict__ Whh2,
                const float* __restrict__ bih2, const float* __restrict__ bhh2,
                const float* __restrict__ fc1w, const float* __restrict__ fc1b,
                const float* __restrict__ fc2w, const float* __restrict__ fc2b,
                float* __restrict__ out)
{
    // Whh2 g/o rows, k-pair packed: [m][j] = {g-row pair, o-row pair}
    __shared__ ulonglong2 s_w2hgo[8][HID];
    // hidden-state broadcast buffers: [warp][elem][16 floats]
    __shared__ float4 s_h1[WPB][2][4];
    __shared__ float4 s_h2[WPB][2][4];
    // FC head
    __shared__ float s_fc1w[(HID / 2) * HID];
    __shared__ float s_fc1b[HID / 2];
    __shared__ float s_fc2w[HID / 2];
    __shared__ float s_fc2b;

    const int tid = threadIdx.x;
    if (tid < 128) {
        const int m = tid >> 4, jj = tid & 15;
        s_w2hgo[m][jj] = make_ulonglong2(
            pack2(Whh2[(32 + jj) * HID + 2 * m], Whh2[(32 + jj) * HID + 2 * m + 1]),
            pack2(Whh2[(48 + jj) * HID + 2 * m], Whh2[(48 + jj) * HID + 2 * m + 1]));
    }
    if (tid < (HID / 2) * HID) s_fc1w[tid] = fc1w[tid];
    if (tid < HID / 2) { s_fc1b[tid] = fc1b[tid]; s_fc2w[tid] = fc2w[tid]; }
    if (tid == 0) s_fc2b = fc2b[0];
    __syncthreads();

    const int lane = tid & 31;
    const int w    = tid >> 5;
    const int e    = lane >> 4;
    const int j    = lane & 15;
    const int b    = (blockIdx.x * WPB + w) * 2 + e;

    const int r0 = j, r1 = j + HID, r2 = j + 2 * HID, r3 = j + 3 * HID;

    // input weights + packed fused-bias constants
    const float wxi = Wih1[r0], wxf = Wih1[r1], wxg = Wih1[r2], wxo = Wih1[r3];
    const ull pb1i = pack2(bih1[r0] + bhh1[r0], 0.f);
    const ull pb1f = pack2(bih1[r1] + bhh1[r1], 0.f);
    const ull pb1g = pack2(bih1[r2] + bhh1[r2], 0.f);
    const ull pb1o = pack2(bih1[r3] + bhh1[r3], 0.f);
    const ull pb2i = pack2(bih2[r0] + bhh2[r0], 0.f);
    const ull pb2f = pack2(bih2[r1] + bhh2[r1], 0.f);
    const ull pb2g = pack2(bih2[r2] + bhh2[r2], 0.f);
    const ull pb2o = pack2(bih2[r3] + bhh2[r3], 0.f);

    // register-resident weight blocks (k-pair packed): 10 arrays x 8 ull = 160 regs
    ull w1i_[8], w1f_[8], w1g_[8], w1o_[8];       // Whh1, all gates (critical path)
    ull w2ii[8], w2if[8], w2ig[8], w2io[8];       // Wih2, all gates
    ull w2hi[8], w2hf[8];                         // Whh2, i/f gates
#pragma unroll
    for (int m = 0; m < 8; ++m) {
        w1i_[m] = pack2(Whh1[r0 * HID + 2 * m], Whh1[r0 * HID + 2 * m + 1]);
        w1f_[m] = pack2(Whh1[r1 * HID + 2 * m], Whh1[r1 * HID + 2 * m + 1]);
        w1g_[m] = pack2(Whh1[r2 * HID + 2 * m], Whh1[r2 * HID + 2 * m + 1]);
        w1o_[m] = pack2(Whh1[r3 * HID + 2 * m], Whh1[r3 * HID + 2 * m + 1]);
        w2ii[m] = pack2(Wih2[r0 * HID + 2 * m], Wih2[r0 * HID + 2 * m + 1]);
        w2if[m] = pack2(Wih2[r1 * HID + 2 * m], Wih2[r1 * HID + 2 * m + 1]);
        w2ig[m] = pack2(Wih2[r2 * HID + 2 * m], Wih2[r2 * HID + 2 * m + 1]);
        w2io[m] = pack2(Wih2[r3 * HID + 2 * m], Wih2[r3 * HID + 2 * m + 1]);
        w2hi[m] = pack2(Whh2[r0 * HID + 2 * m], Whh2[r0 * HID + 2 * m + 1]);
        w2hf[m] = pack2(Whh2[r1 * HID + 2 * m], Whh2[r1 * HID + 2 * m + 1]);
    }

    // carried state; p1* = b1 + Whh1@h1_prev ; p2* = Whh2@h2_prev
    float c1 = 0.f, c2 = 0.f, o_head = 0.f;
    ull p1i = pb1i, p1f = pb1f, p1g = pb1g, p1o = pb1o;
    ull p2i = pack2(0.f, 0.f), p2f = p2i, p2g = p2i, p2o = p2i;

    float* s_h1me = (float*)&s_h1[w][e];
    float* s_h2me = (float*)&s_h2[w][e];
    const ulonglong2* s_h1rd = (const ulonglong2*)&s_h1[w][e];
    const ulonglong2* s_h2rd = (const ulonglong2*)&s_h2[w][e];

    const float* xrow = x + (size_t)b * SEQT;
    float* orow = out + (size_t)b * NOUT;
    float xt = xrow[0];

#pragma unroll 1
    for (int t = 0; t < SEQT + FUT; ++t) {
        const float inp = (t < SEQT) ? xt : o_head;
        xt = xrow[(t + 1) & (SEQT - 1)];

        // ======== layer 1 gates (recurrent part pre-accumulated in p1*) ========
        const float ui = fmaf(wxi, inp, hadd2(p1i));
        const float uf = fmaf(wxf, inp, hadd2(p1f));
        const float ug = fmaf(wxg, inp, hadd2(p1g));
        const float uo = fmaf(wxo, inp, hadd2(p1o));
        const float i1 = sigm(ui), f1 = sigm(uf);
        const float g1 = tanh_ap(ug), o1 = sigm(uo);
        c1 = fmaf(f1, c1, i1 * g1);
        const float h1 = o1 * tanh_ap(c1);

        // ==== broadcast h1 via smem; feeds Wih2 (now) + Whh1 (next, in place) ====
        s_h1me[j] = h1;
        __syncwarp();

        ull a2i = pb2i, a2f = pb2f, a2g = pb2g, a2o = pb2o;
        p1i = pb1i; p1f = pb1f; p1g = pb1g; p1o = pb1o;
#pragma unroll
        for (int q = 0; q < 4; ++q) {
            const ulonglong2 hq = s_h1rd[q];          // 2 packed h-pairs
            a2i = fma2(w2ii[2 * q], hq.x, a2i);
            a2f = fma2(w2if[2 * q], hq.x, a2f);
            a2g = fma2(w2ig[2 * q], hq.x, a2g);
            a2o = fma2(w2io[2 * q], hq.x, a2o);
            p1i = fma2(w1i_[2 * q], hq.x, p1i);
            p1f = fma2(w1f_[2 * q], hq.x, p1f);
            p1g = fma2(w1g_[2 * q], hq.x, p1g);
            p1o = fma2(w1o_[2 * q], hq.x, p1o);
            a2i = fma2(w2ii[2 * q + 1], hq.y, a2i);
            a2f = fma2(w2if[2 * q + 1], hq.y, a2f);
            a2g = fma2(w2ig[2 * q + 1], hq.y, a2g);
            a2o = fma2(w2io[2 * q + 1], hq.y, a2o);
            p1i = fma2(w1i_[2 * q + 1], hq.y, p1i);
            p1f = fma2(w1f_[2 * q + 1], hq.y, p1f);
            p1g = fma2(w1g_[2 * q + 1], hq.y, p1g);
            p1o = fma2(w1o_[2 * q + 1], hq.y, p1o);
        }

        // ======== layer 2 gates ========
        float vi, vf, vg, vo;
        { float lo, hi, lo2, hi2;
          unpack2(a2i, lo, hi); unpack2(p2i, lo2, hi2); vi = (lo + hi) + (lo2 + hi2);
          unpack2(a2f, lo, hi); unpack2(p2f, lo2, hi2); vf = (lo + hi) + (lo2 + hi2);
          unpack2(a2g, lo, hi); unpack2(p2g, lo2, hi2); vg = (lo + hi) + (lo2 + hi2);
          unpack2(a2o, lo, hi); unpack2(p2o, lo2, hi2); vo = (lo + hi) + (lo2 + hi2);
        }
        const float i2 = sigm(vi), f2 = sigm(vf);
        const float g2 = tanh_ap(vg), o2 = sigm(vo);
        c2 = fmaf(f2, c2, i2 * g2);
        const float h2 = o2 * tanh_ap(c2);

        // ==== broadcast h2 via smem; pre-accumulate Whh2 @ h2 in place ====
        s_h2me[j] = h2;
        __syncwarp();

        p2i = pack2(0.f, 0.f); p2f = p2i; p2g = p2i; p2o = p2i;
#pragma unroll
        for (int q = 0; q < 4; ++q) {
            const ulonglong2 hq = s_h2rd[q];
            const ulonglong2 wg0 = s_w2hgo[2 * q][j];
            const ulonglong2 wg1 = s_w2hgo[2 * q + 1][j];
            p2i = fma2(w2hi[2 * q], hq.x, p2i);
            p2f = fma2(w2hf[2 * q], hq.x, p2f);
            p2g = fma2(wg0.x, hq.x, p2g);
            p2o = fma2(wg0.y, hq.x, p2o);
            p2i = fma2(w2hi[2 * q + 1], hq.y, p2i);
            p2f = fma2(w2hf[2 * q + 1], hq.y, p2f);
            p2g = fma2(wg1.x, hq.y, p2g);
            p2o = fma2(wg1.y, hq.y, p2o);
        }

        // ======== head (last teacher step + future steps only) ========
        if (t >= SEQT - 1) {
            const int jj = j & 7;
            float acc = s_fc1b[jj];
            const float* h2f = s_h2me;
#pragma unroll
            for (int k = 0; k < HID; ++k)
                acc = fmaf(s_fc1w[jj * HID + k], h2f[k], acc);
            acc = (acc >= 0.f) ? acc : 0.2f * acc;      // LeakyReLU(0.2)
            float p = (j < 8) ? s_fc2w[jj] * acc : 0.f;
            p += __shfl_xor_sync(0xffffffffu, p, 8);
            p += __shfl_xor_sync(0xffffffffu, p, 4);
            p += __shfl_xor_sync(0xffffffffu, p, 2);
            p += __shfl_xor_sync(0xffffffffu, p, 1);
            o_head = p + s_fc2b;
            if (j == 0) orow[t - (SEQT - 1)] = o_head;
        }
    }
}

extern "C" void kernel_launch(void* const* d_in, const int* in_sizes, int n_in,
                              void* d_out, int out_size)
{
    const float* x    = (const float*)d_in[0];
    const float* Wih1 = (const float*)d_in[1];
    const float* Whh1 = (const float*)d_in[2];
    const float* bih1 = (const float*)d_in[3];
    const float* bhh1 = (const float*)d_in[4];
    const float* Wih2 = (const float*)d_in[5];
    const float* Whh2 = (const float*)d_in[6];
    const float* bih2 = (const float*)d_in[7];
    const float* bhh2 = (const float*)d_in[8];
    const float* fc1w = (const float*)d_in[9];
    const float* fc1b = (const float*)d_in[10];
    const float* fc2w = (const float*)d_in[11];
    const float* fc2b = (const float*)d_in[12];
    float* out = (float*)d_out;

    // 128 blocks x 256 threads: 1 CTA/SM, exactly 2 warps/SMSP everywhere
    lstm_net_kernel<<<BATCH / 16, 32 * WPB>>>(x, Wih1, Whh1, bih1, bhh1,
                                              Wih2, Whh2, bih2, bhh2,
                                              fc1w, fc1b, fc2w, fc2b, out);
}